// round 7
// baseline (speedup 1.0000x reference)
#include <cuda_runtime.h>
#include <cuda_fp16.h>
#include <cstdint>

// ---------------------------------------------------------------------------
// x[4096,8192] fp32, qweight[1024,8192] i32 (4-bit packed along k),
// qzeros[64,1024] i32, scales[64,8192] fp32, bias[8192] fp32
//   -> out[4096,8192] fp32.
// fp16 operands / fp32 accum via mma.sync.m16n8k16 (legal on compute_103;
// tcgen05 is rejected by the harness's virtual arch). Weight dequant is fused
// into the GEMM mainloop; only x is pre-converted (prep_x).
// ---------------------------------------------------------------------------
#define TOKENS   4096
#define INF      8192
#define OUTF     8192
#define KCHUNK   64
#define KCHUNKS  128            // INF / KCHUNK
#define MT       32             // TOKENS / 128
#define NT       32             // OUTF / 256
#define A_TILE   16384          // 128 m-rows * 128B (64 fp16, K-major, SW128)
#define B_TILE   32768          // 256 n-rows * 128B fp16 (dequanted)
#define BRAW_BYTES 8192         // 8 k-rows * 256 n * 4B packed int4
#define SC_BYTES   1024         // 256 fp32 scales
#define Z_BYTES    128          // 32 i32 zeros
#define STAGE_STRIDE 26624      // A(16384)+BRAW(8192)+SC(1024)+Z(128) -> pad to 26*1024
#define A_OFF    0
#define BRAW_OFF 16384
#define SC_OFF   24576
#define Z_OFF    25600
#define NSTAGES  4
#define BF16_OFF (NSTAGES * STAGE_STRIDE)          // 106496
#define SMEM_DYN (BF16_OFF + 2 * B_TILE + 1024)    // 174080 (+align pad)

// scratch: tile-major, pre-swizzled fp16 x (device global, no alloc)
__device__ __align__(1024) unsigned char g_xt[(size_t)MT * KCHUNKS * A_TILE]; // 64 MB

// ---------------------------------------------------------------------------
// helpers
// ---------------------------------------------------------------------------
__device__ __forceinline__ uint32_t smem_to_u32(const void* p) {
    uint32_t a;
    asm("{ .reg .u64 t; cvta.to.shared.u64 t, %1; cvt.u32.u64 %0, t; }" : "=r"(a) : "l"(p));
    return a;
}

#define SWZ(o) ((o) ^ (((o) >> 3) & 0x70))

__device__ __forceinline__ void cp_async16(uint32_t dst, const void* src) {
    asm volatile("cp.async.cg.shared.global [%0], [%1], 16;" :: "r"(dst), "l"(src));
}
#define CP_COMMIT() asm volatile("cp.async.commit_group;" ::: "memory")
#define CP_WAIT(n)  asm volatile("cp.async.wait_group %0;" :: "n"(n) : "memory")

__device__ __forceinline__ void ldsm4(uint32_t& r0, uint32_t& r1, uint32_t& r2, uint32_t& r3,
                                      uint32_t addr) {
    asm volatile("ldmatrix.sync.aligned.m8n8.x4.shared.b16 {%0,%1,%2,%3}, [%4];"
        : "=r"(r0), "=r"(r1), "=r"(r2), "=r"(r3) : "r"(addr));
}

__device__ __forceinline__ void mma16816(float* c,
    uint32_t a0, uint32_t a1, uint32_t a2, uint32_t a3, uint32_t b0, uint32_t b1) {
    asm volatile("mma.sync.aligned.m16n8k16.row.col.f32.f16.f16.f32 "
        "{%0,%1,%2,%3}, {%4,%5,%6,%7}, {%8,%9}, {%0,%1,%2,%3};"
        : "+f"(c[0]), "+f"(c[1]), "+f"(c[2]), "+f"(c[3])
        : "r"(a0), "r"(a1), "r"(a2), "r"(a3), "r"(b0), "r"(b1));
}

__device__ __forceinline__ uint32_t lds32(uint32_t a) {
    uint32_t v; asm volatile("ld.shared.b32 %0, [%1];" : "=r"(v) : "r"(a)); return v;
}
__device__ __forceinline__ float ldsf32(uint32_t a) {
    float v; asm volatile("ld.shared.f32 %0, [%1];" : "=f"(v) : "r"(a)); return v;
}
__device__ __forceinline__ void sts128(uint32_t a, uint32_t x, uint32_t y, uint32_t z, uint32_t w) {
    asm volatile("st.shared.v4.b32 [%0], {%1,%2,%3,%4};" :: "r"(a), "r"(x), "r"(y), "r"(z), "r"(w)
                 : "memory");
}

union HU { unsigned u; __half2 h; };
__device__ __forceinline__ unsigned h2u(__half2 h) { HU t; t.h = h; return t.u; }
__device__ __forceinline__ __half2 u2h(unsigned u) { HU t; t.u = u; return t.h; }

// ---------------------------------------------------------------------------
// prep_x: fp32 -> fp16, tile-major SW128, k-octet permutation (k0,k4)(k1,k5)...
// grid (MT, KCHUNKS), 256 threads
// ---------------------------------------------------------------------------
__global__ void __launch_bounds__(256) prep_x_kernel(const float* __restrict__ x) {
    int mt = blockIdx.x;            // 0..31
    int kc = blockIdx.y;            // 0..127
    unsigned char* tile = g_xt + ((size_t)(mt * KCHUNKS + kc)) * A_TILE;
    const float* xrowbase = x + (size_t)mt * 128 * INF + (size_t)kc * KCHUNK;
    for (int u = threadIdx.x; u < 1024; u += 256) {   // 128 rows * 8 octets
        int row = u >> 3, oct = u & 7;
        const float4* p = (const float4*)(xrowbase + (size_t)row * INF + oct * 8);
        float4 a = p[0];
        float4 b = p[1];
        uint4 o;
        o.x = h2u(__floats2half2_rn(a.x, b.x));   // (k0, k4)
        o.y = h2u(__floats2half2_rn(a.y, b.y));   // (k1, k5)
        o.z = h2u(__floats2half2_rn(a.z, b.z));   // (k2, k6)
        o.w = h2u(__floats2half2_rn(a.w, b.w));   // (k3, k7)
        *(uint4*)(tile + SWZ(row * 128 + oct * 16)) = o;
    }
}

// ---------------------------------------------------------------------------
// fused gemm: 128M x 256N per CTA, 8 warps (2x4) of 64x64, K in 64-chunks.
// Stages carry {A fp16, raw int4 B, scales, zeros}; weights are dequanted
// in-kernel (exact fp16 trick: (1024+w)-(1024+z+1), then scale) into a
// double-buffered swizzled fp16 B tile, one chunk ahead of the MMAs.
// grid (MT, NT) = (32, 32), 256 threads
// ---------------------------------------------------------------------------
__global__ void __launch_bounds__(256, 1) gemm_kernel(
    const int* __restrict__ qw, const int* __restrict__ qz,
    const float* __restrict__ sc,
    const float* __restrict__ bias, float* __restrict__ out)
{
    extern __shared__ unsigned char smem_raw[];
    uint32_t base = (smem_to_u32(smem_raw) + 1023u) & ~1023u;
    uint32_t bfbase = base + BF16_OFF;      // 2 x B_TILE fp16 buffers

    int tid = threadIdx.x, wid = tid >> 5, lane = tid & 31;
    int wm = wid >> 2, wn = wid & 3;        // warp grid 2(m) x 4(n)
    int mt = blockIdx.x, nt = blockIdx.y;
    int ntbase = nt * 256;

    const unsigned char* gA = g_xt + (size_t)mt * KCHUNKS * A_TILE;
    const unsigned char* qwb = (const unsigned char*)qw;
    const unsigned char* scb = (const unsigned char*)sc;
    const unsigned char* qzb = (const unsigned char*)qz;

    // stage fill: A (pre-swizzled, verbatim) + raw B rows + scales + zeros
    auto load_stage = [&](int chunk, int slot) {
        uint32_t sd = base + slot * STAGE_STRIDE;
        const unsigned char* aS = gA + (size_t)chunk * A_TILE;
        #pragma unroll
        for (int i = 0; i < 4; i++)
            cp_async16(sd + (tid + 256 * i) * 16, aS + (size_t)(tid + 256 * i) * 16);
        // 8 qweight rows (k-octets) of this chunk, n-slice [ntbase, ntbase+256)
        const unsigned char* bS = qwb + ((size_t)chunk * 8 * OUTF + ntbase) * 4;
        #pragma unroll
        for (int i = 0; i < 2; i++) {
            int u = tid + 256 * i;            // 0..511
            cp_async16(sd + BRAW_OFF + u * 16,
                       bS + (size_t)(u >> 6) * OUTF * 4 + (u & 63) * 16);
        }
        int g = chunk >> 1;                   // 128-k quant group
        if (tid < 64)
            cp_async16(sd + SC_OFF + tid * 16,
                       scb + ((size_t)g * OUTF + ntbase) * 4 + tid * 16);
        if (tid < 8)
            cp_async16(sd + Z_OFF + tid * 16,
                       qzb + ((size_t)g * (OUTF / 8) + (ntbase >> 3)) * 4 + tid * 16);
    };

    // dequant one chunk's B into fp16 buffer (identical math to old prep_w)
    auto dequant = [&](int chunk) {
        uint32_t sd = base + (chunk & 3) * STAGE_STRIDE;
        uint32_t bb = bfbase + (chunk & 1) * B_TILE;
        uint32_t zq = lds32(sd + Z_OFF + (tid >> 3) * 4);
        unsigned z  = (zq >> ((tid & 7) * 4)) & 0xF;
        unsigned zb = 0x6400u + z + 1u;               // fp16 bits of (1024+z+1), exact
        __half2 zh2 = u2h(zb | (zb << 16));
        __half2 sh2 = __float2half2_rn(ldsf32(sd + SC_OFF + tid * 4));
        const unsigned m = 0x000F000Fu, add = 0x64006400u;
        #pragma unroll
        for (int row = 0; row < 8; row++) {
            unsigned q = lds32(sd + BRAW_OFF + row * 1024 + tid * 4);
            unsigned v0 = (q & m) | add;              // (1024+k0, 1024+k4)
            unsigned v1 = ((q >> 4) & m) | add;       // (k1, k5)
            unsigned v2 = ((q >> 8) & m) | add;       // (k2, k6)
            unsigned v3 = ((q >> 12) & m) | add;      // (k3, k7)
            sts128(bb + SWZ(tid * 128 + row * 16),
                   h2u(__hmul2(__hsub2(u2h(v0), zh2), sh2)),
                   h2u(__hmul2(__hsub2(u2h(v1), zh2), sh2)),
                   h2u(__hmul2(__hsub2(u2h(v2), zh2), sh2)),
                   h2u(__hmul2(__hsub2(u2h(v3), zh2), sh2)));
        }
    };

    // ldmatrix per-lane geometry (validated in rounds 3/6).
    int gq = lane >> 3, r = lane & 7;
    int aRow0 = wm * 64 + (gq & 1) * 8 + r;   int aGh = gq >> 1;
    int bRow0 = wn * 64 + (gq >> 1) * 8 + r;  int bGl = gq & 1;

    float acc[4][8][4];
    #pragma unroll
    for (int i = 0; i < 4; i++)
        #pragma unroll
        for (int j = 0; j < 8; j++)
            #pragma unroll
            for (int k = 0; k < 4; k++) acc[i][j][k] = 0.f;

    uint32_t afr[2][4][4], bfr[2][4][4];

#define PREFETCH(BUF, ABASE, BBASE, C) do {                                       \
        uint32_t _sA = (ABASE), _sB = (BBASE);                                    \
        _Pragma("unroll")                                                         \
        for (int mb = 0; mb < 4; mb++) {                                          \
            uint32_t off = (uint32_t)(aRow0 + mb * 16) * 128u                     \
                         + (uint32_t)(((2 * (C) + aGh) ^ r) << 4);                \
            ldsm4(afr[BUF][mb][0], afr[BUF][mb][1], afr[BUF][mb][2],              \
                  afr[BUF][mb][3], _sA + off);                                    \
        }                                                                         \
        _Pragma("unroll")                                                         \
        for (int p = 0; p < 4; p++) {                                             \
            uint32_t off = (uint32_t)(bRow0 + p * 16) * 128u                      \
                         + (uint32_t)(((2 * (C) + bGl) ^ r) << 4);                \
            ldsm4(bfr[BUF][p][0], bfr[BUF][p][1], bfr[BUF][p][2],                 \
                  bfr[BUF][p][3], _sB + off);                                     \
        }                                                                         \
    } while (0)

#define MMASTEP(BUF) do {                                                         \
        _Pragma("unroll")                                                         \
        for (int mb = 0; mb < 4; mb++)                                            \
            _Pragma("unroll")                                                     \
            for (int p = 0; p < 4; p++) {                                         \
                mma16816(acc[mb][2 * p],     afr[BUF][mb][0], afr[BUF][mb][1],    \
                         afr[BUF][mb][2], afr[BUF][mb][3],                        \
                         bfr[BUF][p][0], bfr[BUF][p][1]);                         \
                mma16816(acc[mb][2 * p + 1], afr[BUF][mb][0], afr[BUF][mb][1],    \
                         afr[BUF][mb][2], afr[BUF][mb][3],                        \
                         bfr[BUF][p][2], bfr[BUF][p][3]);                         \
            }                                                                     \
    } while (0)

    // prologue: stages 0..2 in flight; stage 0 resident -> dequant chunk 0
    #pragma unroll
    for (int j = 0; j < NSTAGES - 1; j++) { load_stage(j, j); CP_COMMIT(); }
    CP_WAIT(2);
    __syncthreads();
    dequant(0);
    __syncthreads();

    #pragma unroll 1
    for (int it = 0; it < KCHUNKS; it++) {
        if (it + 3 < KCHUNKS) load_stage(it + 3, (it + 3) & 3);
        CP_COMMIT();
        CP_WAIT(2);                         // chunk it+1 stage resident (for dequant)

        uint32_t aB = base + (it & 3) * STAGE_STRIDE;
        uint32_t bB = bfbase + (it & 1) * B_TILE;
        PREFETCH(0, aB, bB, 0);
        PREFETCH(1, aB, bB, 1); MMASTEP(0);
        PREFETCH(0, aB, bB, 2); MMASTEP(1);
        PREFETCH(1, aB, bB, 3); MMASTEP(0);
        MMASTEP(1);

        if (it + 1 < KCHUNKS) dequant(it + 1);   // fills other B buffer
        __syncthreads();                          // publish dequant; free stage (it)&3
    }
    CP_WAIT(0);

#undef PREFETCH
#undef MMASTEP

    // epilogue: acc frag (c0,c1)=(row l/4, col 2(l%4),+1), (c2,c3)=(row+8, same)
    int rowBase = mt * 128 + wm * 64 + (lane >> 2);
    int colBase = ntbase + wn * 64 + 2 * (lane & 3);
    #pragma unroll
    for (int nb = 0; nb < 8; nb++) {
        int n0 = colBase + nb * 8;
        float2 bv = *(const float2*)(bias + n0);
        #pragma unroll
        for (int mb = 0; mb < 4; mb++) {
            int m0 = rowBase + mb * 16;
            float2 v0 = { acc[mb][nb][0] + bv.x, acc[mb][nb][1] + bv.y };
            float2 v1 = { acc[mb][nb][2] + bv.x, acc[mb][nb][3] + bv.y };
            *(float2*)(out + (size_t)m0 * OUTF + n0) = v0;
            *(float2*)(out + (size_t)(m0 + 8) * OUTF + n0) = v1;
        }
    }
}

// ---------------------------------------------------------------------------
// launch
// ---------------------------------------------------------------------------
extern "C" void kernel_launch(void* const* d_in, const int* in_sizes, int n_in,
                              void* d_out, int out_size) {
    const float* x      = (const float*)d_in[0];
    const int*   qw     = (const int*)d_in[1];
    const int*   qz     = (const int*)d_in[2];
    const float* scales = (const float*)d_in[3];
    const float* bias   = (const float*)d_in[4];
    float* out = (float*)d_out;

    static int configured = 0;
    if (!configured) {
        cudaFuncSetAttribute(gemm_kernel, cudaFuncAttributeMaxDynamicSharedMemorySize, SMEM_DYN);
        configured = 1;
    }

    dim3 gx(MT, KCHUNKS);
    prep_x_kernel<<<gx, 256>>>(x);

    dim3 gg(MT, NT);
    gemm_kernel<<<gg, 256, SMEM_DYN>>>(qw, qz, scales, bias, out);
}

// round 8
// speedup vs baseline: 1.1636x; 1.1636x over previous
#include <cuda_runtime.h>
#include <cuda_fp16.h>
#include <cstdint>

// ---------------------------------------------------------------------------
// x[4096,8192] fp32, qweight[1024,8192] i32 (4-bit packed along k),
// qzeros[64,1024] i32, scales[64,8192] fp32, bias[8192] fp32
//   -> out[4096,8192] fp32.
// fp16 operands / fp32 accum via mma.sync.m16n8k16 (legal on compute_103;
// tcgen05 is rejected by the harness's virtual arch). Weight dequant fused
// into the GEMM mainloop, INTERLEAVED between MMA steps so it issues in the
// tensor-pipe shadow (round-7 ran it serially after the MMAs -> +400us).
// ---------------------------------------------------------------------------
#define TOKENS   4096
#define INF      8192
#define OUTF     8192
#define KCHUNK   64
#define KCHUNKS  128            // INF / KCHUNK
#define MT       32             // TOKENS / 128
#define NT       32             // OUTF / 256
#define A_TILE   16384          // 128 m-rows * 128B (64 fp16, K-major, SW128)
#define B_TILE   32768          // 256 n-rows * 128B fp16 (dequanted)
#define BRAW_OFF 16384          // 8 k-rows * 256 n * 4B packed int4 (8KB)
#define SC_OFF   24576          // 256 fp32 scales (1KB)
#define Z_OFF    25600          // 32 i32 zeros (128B)
#define STAGE_STRIDE 26624      // padded to 26KB
#define NSTAGES  4
#define BF16_OFF (NSTAGES * STAGE_STRIDE)          // 106496
#define SMEM_DYN (BF16_OFF + 2 * B_TILE + 1024)    // ~171KB -> 1 CTA/SM

// scratch: tile-major, pre-swizzled fp16 x (device global, no alloc)
__device__ __align__(1024) unsigned char g_xt[(size_t)MT * KCHUNKS * A_TILE]; // 64 MB

// ---------------------------------------------------------------------------
// helpers
// ---------------------------------------------------------------------------
__device__ __forceinline__ uint32_t smem_to_u32(const void* p) {
    uint32_t a;
    asm("{ .reg .u64 t; cvta.to.shared.u64 t, %1; cvt.u32.u64 %0, t; }" : "=r"(a) : "l"(p));
    return a;
}

#define SWZ(o) ((o) ^ (((o) >> 3) & 0x70))

__device__ __forceinline__ void cp_async16(uint32_t dst, const void* src) {
    asm volatile("cp.async.cg.shared.global [%0], [%1], 16;" :: "r"(dst), "l"(src));
}
#define CP_COMMIT() asm volatile("cp.async.commit_group;" ::: "memory")
#define CP_WAIT(n)  asm volatile("cp.async.wait_group %0;" :: "n"(n) : "memory")

__device__ __forceinline__ void ldsm4(uint32_t& r0, uint32_t& r1, uint32_t& r2, uint32_t& r3,
                                      uint32_t addr) {
    asm volatile("ldmatrix.sync.aligned.m8n8.x4.shared.b16 {%0,%1,%2,%3}, [%4];"
        : "=r"(r0), "=r"(r1), "=r"(r2), "=r"(r3) : "r"(addr));
}

__device__ __forceinline__ void mma16816(float* c,
    uint32_t a0, uint32_t a1, uint32_t a2, uint32_t a3, uint32_t b0, uint32_t b1) {
    asm volatile("mma.sync.aligned.m16n8k16.row.col.f32.f16.f16.f32 "
        "{%0,%1,%2,%3}, {%4,%5,%6,%7}, {%8,%9}, {%0,%1,%2,%3};"
        : "+f"(c[0]), "+f"(c[1]), "+f"(c[2]), "+f"(c[3])
        : "r"(a0), "r"(a1), "r"(a2), "r"(a3), "r"(b0), "r"(b1));
}

__device__ __forceinline__ uint32_t lds32(uint32_t a) {
    uint32_t v; asm volatile("ld.shared.b32 %0, [%1];" : "=r"(v) : "r"(a)); return v;
}
__device__ __forceinline__ float ldsf32(uint32_t a) {
    float v; asm volatile("ld.shared.f32 %0, [%1];" : "=f"(v) : "r"(a)); return v;
}
__device__ __forceinline__ void sts128(uint32_t a, uint32_t x, uint32_t y, uint32_t z, uint32_t w) {
    asm volatile("st.shared.v4.b32 [%0], {%1,%2,%3,%4};" :: "r"(a), "r"(x), "r"(y), "r"(z), "r"(w)
                 : "memory");
}

union HU { unsigned u; __half2 h; };
__device__ __forceinline__ unsigned h2u(__half2 h) { HU t; t.h = h; return t.u; }
__device__ __forceinline__ __half2 u2h(unsigned u) { HU t; t.u = u; return t.h; }

// ---------------------------------------------------------------------------
// prep_x: fp32 -> fp16, tile-major SW128, k-octet permutation (k0,k4)(k1,k5)...
// grid (MT, KCHUNKS), 256 threads
// ---------------------------------------------------------------------------
__global__ void __launch_bounds__(256) prep_x_kernel(const float* __restrict__ x) {
    int mt = blockIdx.x;            // 0..31
    int kc = blockIdx.y;            // 0..127
    unsigned char* tile = g_xt + ((size_t)(mt * KCHUNKS + kc)) * A_TILE;
    const float* xrowbase = x + (size_t)mt * 128 * INF + (size_t)kc * KCHUNK;
    for (int u = threadIdx.x; u < 1024; u += 256) {   // 128 rows * 8 octets
        int row = u >> 3, oct = u & 7;
        const float4* p = (const float4*)(xrowbase + (size_t)row * INF + oct * 8);
        float4 a = p[0];
        float4 b = p[1];
        uint4 o;
        o.x = h2u(__floats2half2_rn(a.x, b.x));   // (k0, k4)
        o.y = h2u(__floats2half2_rn(a.y, b.y));   // (k1, k5)
        o.z = h2u(__floats2half2_rn(a.z, b.z));   // (k2, k6)
        o.w = h2u(__floats2half2_rn(a.w, b.w));   // (k3, k7)
        *(uint4*)(tile + SWZ(row * 128 + oct * 16)) = o;
    }
}

// ---------------------------------------------------------------------------
// fused gemm: 128M x 256N per CTA, 8 warps (2x4) of 64x64, K in 64-chunks.
// Stage = {A fp16 16KB, raw int4 B 8KB, scales 1KB, zeros 128B}. Dequant of
// chunk it+1 (exact fp16: (1024+w)-(1024+z+1), then scale) is interleaved
// between chunk it's MMA steps, writing a double-buffered fp16 B tile.
// grid (MT, NT) = (32, 32), 256 threads
// ---------------------------------------------------------------------------
__global__ void __launch_bounds__(256, 1) gemm_kernel(
    const int* __restrict__ qw, const int* __restrict__ qz,
    const float* __restrict__ sc,
    const float* __restrict__ bias, float* __restrict__ out)
{
    extern __shared__ unsigned char smem_raw[];
    uint32_t base = (smem_to_u32(smem_raw) + 1023u) & ~1023u;
    uint32_t bfbase = base + BF16_OFF;      // 2 x B_TILE fp16 buffers

    int tid = threadIdx.x, wid = tid >> 5, lane = tid & 31;
    int wm = wid >> 2, wn = wid & 3;        // warp grid 2(m) x 4(n)
    int mt = blockIdx.x, nt = blockIdx.y;
    int ntbase = nt * 256;

    const unsigned char* gA = g_xt + (size_t)mt * KCHUNKS * A_TILE;
    const unsigned char* qwb = (const unsigned char*)qw;
    const unsigned char* scb = (const unsigned char*)sc;
    const unsigned char* qzb = (const unsigned char*)qz;

    // stage fill: A (pre-swizzled, verbatim) + raw B rows + scales + zeros
    auto load_stage = [&](int chunk, int slot) {
        uint32_t sd = base + slot * STAGE_STRIDE;
        const unsigned char* aS = gA + (size_t)chunk * A_TILE;
        #pragma unroll
        for (int i = 0; i < 4; i++)
            cp_async16(sd + (tid + 256 * i) * 16, aS + (size_t)(tid + 256 * i) * 16);
        const unsigned char* bS = qwb + ((size_t)chunk * 8 * OUTF + ntbase) * 4;
        #pragma unroll
        for (int i = 0; i < 2; i++) {
            int u = tid + 256 * i;            // 0..511
            cp_async16(sd + BRAW_OFF + u * 16,
                       bS + (size_t)(u >> 6) * OUTF * 4 + (u & 63) * 16);
        }
        int g = chunk >> 1;                   // 128-k quant group
        if (tid < 64)
            cp_async16(sd + SC_OFF + tid * 16,
                       scb + ((size_t)g * OUTF + ntbase) * 4 + tid * 16);
        if (tid < 8)
            cp_async16(sd + Z_OFF + tid * 16,
                       qzb + ((size_t)g * (OUTF / 8) + (ntbase >> 3)) * 4 + tid * 16);
    };

    // ldmatrix per-lane geometry (validated rounds 3/6/7).
    int gq = lane >> 3, r = lane & 7;
    int aRow0 = wm * 64 + (gq & 1) * 8 + r;   int aGh = gq >> 1;
    int bRow0 = wn * 64 + (gq >> 1) * 8 + r;  int bGl = gq & 1;

    float acc[4][8][4];
    #pragma unroll
    for (int i = 0; i < 4; i++)
        #pragma unroll
        for (int j = 0; j < 8; j++)
            #pragma unroll
            for (int k = 0; k < 4; k++) acc[i][j][k] = 0.f;

    uint32_t afr[2][4][4], bfr[2][4][4];
    const unsigned dm = 0x000F000Fu, dadd = 0x64006400u;

#define PREFETCH(BUF, ABASE, BBASE, C) do {                                       \
        uint32_t _sA = (ABASE), _sB = (BBASE);                                    \
        _Pragma("unroll")                                                         \
        for (int mb = 0; mb < 4; mb++) {                                          \
            uint32_t off = (uint32_t)(aRow0 + mb * 16) * 128u                     \
                         + (uint32_t)(((2 * (C) + aGh) ^ r) << 4);                \
            ldsm4(afr[BUF][mb][0], afr[BUF][mb][1], afr[BUF][mb][2],              \
                  afr[BUF][mb][3], _sA + off);                                    \
        }                                                                         \
        _Pragma("unroll")                                                         \
        for (int p = 0; p < 4; p++) {                                             \
            uint32_t off = (uint32_t)(bRow0 + p * 16) * 128u                      \
                         + (uint32_t)(((2 * (C) + bGl) ^ r) << 4);                \
            ldsm4(bfr[BUF][p][0], bfr[BUF][p][1], bfr[BUF][p][2],                 \
                  bfr[BUF][p][3], _sB + off);                                     \
        }                                                                         \
    } while (0)

#define MMASTEP(BUF) do {                                                         \
        _Pragma("unroll")                                                         \
        for (int mb = 0; mb < 4; mb++)                                            \
            _Pragma("unroll")                                                     \
            for (int p = 0; p < 4; p++) {                                         \
                mma16816(acc[mb][2 * p],     afr[BUF][mb][0], afr[BUF][mb][1],    \
                         afr[BUF][mb][2], afr[BUF][mb][3],                        \
                         bfr[BUF][p][0], bfr[BUF][p][1]);                         \
                mma16816(acc[mb][2 * p + 1], afr[BUF][mb][0], afr[BUF][mb][1],    \
                         afr[BUF][mb][2], afr[BUF][mb][3],                        \
                         bfr[BUF][p][2], bfr[BUF][p][3]);                         \
            }                                                                     \
    } while (0)

#define DQROW(R) do {                                                             \
        unsigned _q = qv[R];                                                      \
        unsigned _v0 = (_q & dm) | dadd;                                          \
        unsigned _v1 = ((_q >> 4) & dm) | dadd;                                   \
        unsigned _v2 = ((_q >> 8) & dm) | dadd;                                   \
        unsigned _v3 = ((_q >> 12) & dm) | dadd;                                  \
        sts128(bbn + SWZ(tid * 128 + (R) * 16),                                   \
               h2u(__hmul2(__hsub2(u2h(_v0), zh2), sh2)),                         \
               h2u(__hmul2(__hsub2(u2h(_v1), zh2), sh2)),                         \
               h2u(__hmul2(__hsub2(u2h(_v2), zh2), sh2)),                         \
               h2u(__hmul2(__hsub2(u2h(_v3), zh2), sh2)));                        \
    } while (0)

    // prologue: stages 0..2 in flight; stage 0 resident -> dequant chunk 0
    #pragma unroll
    for (int j = 0; j < NSTAGES - 1; j++) { load_stage(j, j); CP_COMMIT(); }
    CP_WAIT(2);               // group 0 complete
    __syncthreads();          // ...and visible to all threads
    {
        uint32_t sdn = base, bbn = bfbase;
        uint32_t zq = lds32(sdn + Z_OFF + (tid >> 3) * 4);
        float scf = ldsf32(sdn + SC_OFF + tid * 4);
        unsigned z  = (zq >> ((tid & 7) * 4)) & 0xF;
        unsigned zb = 0x6400u + z + 1u;          // fp16 bits of (1024+z+1), exact
        __half2 zh2 = u2h(zb | (zb << 16));
        __half2 sh2 = __float2half2_rn(scf);
        uint32_t qv[8];
        #pragma unroll
        for (int rr = 0; rr < 8; rr++) qv[rr] = lds32(sdn + BRAW_OFF + rr * 1024 + tid * 4);
        DQROW(0); DQROW(1); DQROW(2); DQROW(3);
        DQROW(4); DQROW(5); DQROW(6); DQROW(7);
    }

    #pragma unroll 1
    for (int it = 0; it < KCHUNKS; it++) {
        CP_WAIT(1);           // completes group it+1 (raw for this iter's dequant)
        __syncthreads();      // publish bf((it)&1); stage it+1 visible; safe slot reuse
        if (it + 3 < KCHUNKS) load_stage(it + 3, (it + 3) & 3);
        CP_COMMIT();

        uint32_t aB  = base + (it & 3) * STAGE_STRIDE;
        uint32_t bB  = bfbase + (it & 1) * B_TILE;
        uint32_t sdn = base + ((it + 1) & 3) * STAGE_STRIDE;
        uint32_t bbn = bfbase + ((it + 1) & 1) * B_TILE;

        // issue all dequant loads up front (latency hides under first MMAs);
        // last iter (it=127) dequants stale data into the unread buffer: benign.
        uint32_t zq = lds32(sdn + Z_OFF + (tid >> 3) * 4);
        float scf = ldsf32(sdn + SC_OFF + tid * 4);
        uint32_t qv[8];
        #pragma unroll
        for (int rr = 0; rr < 8; rr++) qv[rr] = lds32(sdn + BRAW_OFF + rr * 1024 + tid * 4);
        unsigned z  = (zq >> ((tid & 7) * 4)) & 0xF;
        unsigned zb = 0x6400u + z + 1u;
        __half2 zh2 = u2h(zb | (zb << 16));
        __half2 sh2 = __float2half2_rn(scf);

        PREFETCH(0, aB, bB, 0);
        PREFETCH(1, aB, bB, 1); MMASTEP(0); DQROW(0); DQROW(1);
        PREFETCH(0, aB, bB, 2); MMASTEP(1); DQROW(2); DQROW(3);
        PREFETCH(1, aB, bB, 3); MMASTEP(0); DQROW(4); DQROW(5);
        MMASTEP(1);             DQROW(6); DQROW(7);
    }
    CP_WAIT(0);

#undef PREFETCH
#undef MMASTEP
#undef DQROW

    // epilogue: acc frag (c0,c1)=(row l/4, col 2(l%4),+1), (c2,c3)=(row+8, same)
    int rowBase = mt * 128 + wm * 64 + (lane >> 2);
    int colBase = ntbase + wn * 64 + 2 * (lane & 3);
    #pragma unroll
    for (int nb = 0; nb < 8; nb++) {
        int n0 = colBase + nb * 8;
        float2 bv = *(const float2*)(bias + n0);
        #pragma unroll
        for (int mb = 0; mb < 4; mb++) {
            int m0 = rowBase + mb * 16;
            float2 v0 = { acc[mb][nb][0] + bv.x, acc[mb][nb][1] + bv.y };
            float2 v1 = { acc[mb][nb][2] + bv.x, acc[mb][nb][3] + bv.y };
            *(float2*)(out + (size_t)m0 * OUTF + n0) = v0;
            *(float2*)(out + (size_t)(m0 + 8) * OUTF + n0) = v1;
        }
    }
}

// ---------------------------------------------------------------------------
// launch
// ---------------------------------------------------------------------------
extern "C" void kernel_launch(void* const* d_in, const int* in_sizes, int n_in,
                              void* d_out, int out_size) {
    const float* x      = (const float*)d_in[0];
    const int*   qw     = (const int*)d_in[1];
    const int*   qz     = (const int*)d_in[2];
    const float* scales = (const float*)d_in[3];
    const float* bias   = (const float*)d_in[4];
    float* out = (float*)d_out;

    static int configured = 0;
    if (!configured) {
        cudaFuncSetAttribute(gemm_kernel, cudaFuncAttributeMaxDynamicSharedMemorySize, SMEM_DYN);
        configured = 1;
    }

    dim3 gx(MT, KCHUNKS);
    prep_x_kernel<<<gx, 256>>>(x);

    dim3 gg(MT, NT);
    gemm_kernel<<<gg, 256, SMEM_DYN>>>(qw, qz, scales, bias, out);
}

// round 9
// speedup vs baseline: 1.1839x; 1.0175x over previous
#include <cuda_runtime.h>
#include <cuda_fp16.h>
#include <cstdint>

// ---------------------------------------------------------------------------
// x[4096,8192] fp32, qweight[1024,8192] i32 (4-bit packed along k),
// qzeros[64,1024] i32, scales[64,8192] fp32, bias[8192] fp32
//   -> out[4096,8192] fp32.
// Two-pass: prep kernels write pre-swizzled fp16 tiles (exact-fp16 dequant);
// gemm uses mma.sync.m16n8k16 fp16->fp32 (tcgen05 is rejected by the
// harness's compute_103 virtual arch). This round: 512-thread gemm CTA
// (16 warps -> 4 warps/SMSP) for latency hiding; single-buffered fragments.
// ---------------------------------------------------------------------------
#define TOKENS   4096
#define INF      8192
#define OUTF     8192
#define KCHUNK   64
#define KCHUNKS  128            // INF / KCHUNK
#define MT       32             // TOKENS / 128
#define NT       32             // OUTF / 256
#define A_TILE   16384          // 128 m-rows * 128B (64 fp16, K-major, SW128)
#define B_TILE   32768          // 256 n-rows * 128B
#define STAGE_BYTES (A_TILE + B_TILE)
#define NSTAGES  4
#define SMEM_DYN (NSTAGES * STAGE_BYTES + 1024)   // ~193KB -> 1 CTA/SM

// scratch: tile-major, pre-swizzled fp16 operands (device globals, no alloc)
__device__ __align__(1024) unsigned char g_xt[(size_t)MT * KCHUNKS * A_TILE]; // 64 MB
__device__ __align__(1024) unsigned char g_wt[(size_t)NT * KCHUNKS * B_TILE]; // 128 MB

// ---------------------------------------------------------------------------
// helpers
// ---------------------------------------------------------------------------
__device__ __forceinline__ uint32_t smem_to_u32(const void* p) {
    uint32_t a;
    asm("{ .reg .u64 t; cvta.to.shared.u64 t, %1; cvt.u32.u64 %0, t; }" : "=r"(a) : "l"(p));
    return a;
}

#define SWZ(o) ((o) ^ (((o) >> 3) & 0x70))

__device__ __forceinline__ void cp_async16(uint32_t dst, const void* src) {
    asm volatile("cp.async.cg.shared.global [%0], [%1], 16;" :: "r"(dst), "l"(src));
}
#define CP_COMMIT() asm volatile("cp.async.commit_group;" ::: "memory")
#define CP_WAIT(n)  asm volatile("cp.async.wait_group %0;" :: "n"(n) : "memory")

__device__ __forceinline__ void ldsm4(uint32_t& r0, uint32_t& r1, uint32_t& r2, uint32_t& r3,
                                      uint32_t addr) {
    asm volatile("ldmatrix.sync.aligned.m8n8.x4.shared.b16 {%0,%1,%2,%3}, [%4];"
        : "=r"(r0), "=r"(r1), "=r"(r2), "=r"(r3) : "r"(addr));
}

__device__ __forceinline__ void mma16816(float* c,
    uint32_t a0, uint32_t a1, uint32_t a2, uint32_t a3, uint32_t b0, uint32_t b1) {
    asm volatile("mma.sync.aligned.m16n8k16.row.col.f32.f16.f16.f32 "
        "{%0,%1,%2,%3}, {%4,%5,%6,%7}, {%8,%9}, {%0,%1,%2,%3};"
        : "+f"(c[0]), "+f"(c[1]), "+f"(c[2]), "+f"(c[3])
        : "r"(a0), "r"(a1), "r"(a2), "r"(a3), "r"(b0), "r"(b1));
}

union HU { unsigned u; __half2 h; };
__device__ __forceinline__ unsigned h2u(__half2 h) { HU t; t.h = h; return t.u; }
__device__ __forceinline__ __half2 u2h(unsigned u) { HU t; t.u = u; return t.h; }

// ---------------------------------------------------------------------------
// prep_x: fp32 -> fp16, tile-major SW128, k-octet permutation (k0,k4)(k1,k5)...
// grid (MT, KCHUNKS), 256 threads
// ---------------------------------------------------------------------------
__global__ void __launch_bounds__(256) prep_x_kernel(const float* __restrict__ x) {
    int mt = blockIdx.x;            // 0..31
    int kc = blockIdx.y;            // 0..127
    unsigned char* tile = g_xt + ((size_t)(mt * KCHUNKS + kc)) * A_TILE;
    const float* xrowbase = x + (size_t)mt * 128 * INF + (size_t)kc * KCHUNK;
    for (int u = threadIdx.x; u < 1024; u += 256) {   // 128 rows * 8 octets
        int row = u >> 3, oct = u & 7;
        const float4* p = (const float4*)(xrowbase + (size_t)row * INF + oct * 8);
        float4 a = p[0];
        float4 b = p[1];
        uint4 o;
        o.x = h2u(__floats2half2_rn(a.x, b.x));   // (k0, k4)
        o.y = h2u(__floats2half2_rn(a.y, b.y));   // (k1, k5)
        o.z = h2u(__floats2half2_rn(a.z, b.z));   // (k2, k6)
        o.w = h2u(__floats2half2_rn(a.w, b.w));   // (k3, k7)
        *(uint4*)(tile + SWZ(row * 128 + oct * 16)) = o;
    }
}

// ---------------------------------------------------------------------------
// prep_w: int4 unpack + dequant -> fp16, n-major K-contiguous tiles, SW128,
// same k-octet permutation. The fp16 math is EXACT until the final scale mul:
// (1024+w) - (1024+z+1) = w-z-1 with all integers exactly representable.
// grid (OUTF/256, INF/8) = (32, 1024), 256 threads
// ---------------------------------------------------------------------------
__global__ void __launch_bounds__(256) prep_w_kernel(
    const int* __restrict__ qw, const int* __restrict__ qz, const float* __restrict__ sc)
{
    int n  = blockIdx.x * 256 + threadIdx.x;   // 0..8191
    int kr = blockIdx.y;                       // packed k-octet row, 0..1023
    int kc  = kr >> 3;                         // 64-k chunk index
    int oct = kr & 7;                          // octet within chunk
    int g   = kr >> 4;                         // 128-k quant group

    unsigned q  = (unsigned)qw[(size_t)kr * OUTF + n];
    unsigned zq = (unsigned)qz[(size_t)g * (OUTF / 8) + (n >> 3)];
    unsigned z  = (zq >> ((n & 7) * 4)) & 0xF;
    unsigned zb = 0x6400u + z + 1u;            // fp16 bits of (1024 + z + 1), exact
    __half2 zh2 = u2h(zb | (zb << 16));
    __half2 sh2 = __float2half2_rn(sc[(size_t)g * OUTF + n]);

    const unsigned m = 0x000F000Fu, add = 0x64006400u;
    unsigned v0 = (q & m) | add;               // (1024+k0, 1024+k4)
    unsigned v1 = ((q >> 4) & m) | add;        // (k1, k5)
    unsigned v2 = ((q >> 8) & m) | add;        // (k2, k6)
    unsigned v3 = ((q >> 12) & m) | add;       // (k3, k7)
    uint4 o;
    o.x = h2u(__hmul2(__hsub2(u2h(v0), zh2), sh2));
    o.y = h2u(__hmul2(__hsub2(u2h(v1), zh2), sh2));
    o.z = h2u(__hmul2(__hsub2(u2h(v2), zh2), sh2));
    o.w = h2u(__hmul2(__hsub2(u2h(v3), zh2), sh2));

    int nt = n >> 8;          // 256-wide n tile
    int rr = n & 255;         // n-row within tile
    unsigned char* tile = g_wt + ((size_t)(nt * KCHUNKS + kc)) * B_TILE;
    *(uint4*)(tile + SWZ(rr * 128 + oct * 16)) = o;
}

// ---------------------------------------------------------------------------
// gemm: 128M x 256N per CTA, 16 warps (2m x 8n) of 64x32, K in 64-chunks,
// 4-stage cp.async pipeline, mma.sync m16n8k16 fp16->fp32.
// 512 threads -> 4 warps/SMSP: latency hidden by warp parallelism, so
// fragments are single-buffered (keeps regs ~110 < 126 cap).
// grid (MT, NT) = (32, 32), 512 threads
// ---------------------------------------------------------------------------
__global__ void __launch_bounds__(512, 1) gemm_kernel(
    const float* __restrict__ bias, float* __restrict__ out)
{
    extern __shared__ unsigned char smem_raw[];
    uint32_t base = (smem_to_u32(smem_raw) + 1023u) & ~1023u;

    int tid = threadIdx.x, wid = tid >> 5, lane = tid & 31;
    int wm = wid >> 3, wn = wid & 7;           // warp grid 2(m) x 8(n)
    int mt = blockIdx.x, nt = blockIdx.y;

    const unsigned char* gA = g_xt + (size_t)mt * KCHUNKS * A_TILE;
    const unsigned char* gB = g_wt + (size_t)nt * KCHUNKS * B_TILE;

    // cp.async stage fill: data is pre-swizzled in gmem -> verbatim 16B copies
    auto load_stage = [&](int chunk, int slot) {
        uint32_t sd = base + slot * STAGE_BYTES;
        const unsigned char* aS = gA + (size_t)chunk * A_TILE;
        const unsigned char* bS = gB + (size_t)chunk * B_TILE;
        #pragma unroll
        for (int i = 0; i < 2; i++)
            cp_async16(sd + (tid + 512 * i) * 16, aS + (size_t)(tid + 512 * i) * 16);
        #pragma unroll
        for (int i = 0; i < 4; i++)
            cp_async16(sd + A_TILE + (tid + 512 * i) * 16, bS + (size_t)(tid + 512 * i) * 16);
    };

    // ldmatrix per-lane geometry (validated rounds 3/6/7/8).
    int gq = lane >> 3, r = lane & 7;
    int aRow0 = wm * 64 + (gq & 1) * 8 + r;   int aGh = gq >> 1;
    int bRow0 = wn * 32 + (gq >> 1) * 8 + r;  int bGl = gq & 1;

    float acc[4][4][4];                        // [mb][nb=2p+j][frag]
    #pragma unroll
    for (int i = 0; i < 4; i++)
        #pragma unroll
        for (int j = 0; j < 4; j++)
            #pragma unroll
            for (int k = 0; k < 4; k++) acc[i][j][k] = 0.f;

    // prologue: stages 0..2 in flight
    #pragma unroll
    for (int j = 0; j < NSTAGES - 1; j++) { load_stage(j, j); CP_COMMIT(); }

    #pragma unroll 1
    for (int it = 0; it < KCHUNKS; it++) {
        CP_WAIT(1);            // stages it, it+1 complete
        __syncthreads();       // visible to all; safe to overwrite slot (it+3)&3
        if (it + NSTAGES - 1 < KCHUNKS) load_stage(it + NSTAGES - 1, (it + NSTAGES - 1) & 3);
        CP_COMMIT();

        uint32_t sA = base + (it & 3) * STAGE_BYTES;
        uint32_t sB = sA + A_TILE;
        #pragma unroll
        for (int c = 0; c < 4; c++) {          // four k16 steps
            uint32_t a[4][4], b[2][4];
            #pragma unroll
            for (int mb = 0; mb < 4; mb++) {
                uint32_t off = (uint32_t)(aRow0 + mb * 16) * 128u
                             + (uint32_t)(((2 * c + aGh) ^ r) << 4);
                ldsm4(a[mb][0], a[mb][1], a[mb][2], a[mb][3], sA + off);
            }
            #pragma unroll
            for (int p = 0; p < 2; p++) {
                uint32_t off = (uint32_t)(bRow0 + p * 16) * 128u
                             + (uint32_t)(((2 * c + bGl) ^ r) << 4);
                ldsm4(b[p][0], b[p][1], b[p][2], b[p][3], sB + off);
            }
            #pragma unroll
            for (int mb = 0; mb < 4; mb++)
                #pragma unroll
                for (int p = 0; p < 2; p++) {
                    mma16816(acc[mb][2 * p],     a[mb][0], a[mb][1], a[mb][2], a[mb][3],
                             b[p][0], b[p][1]);
                    mma16816(acc[mb][2 * p + 1], a[mb][0], a[mb][1], a[mb][2], a[mb][3],
                             b[p][2], b[p][3]);
                }
        }
    }
    CP_WAIT(0);   // drain outstanding copies before exit

    // epilogue: acc frag (c0,c1)=(row l/4, col 2(l%4),+1), (c2,c3)=(row+8, same)
    int rowBase = mt * 128 + wm * 64 + (lane >> 2);
    int colBase = nt * 256 + wn * 32 + 2 * (lane & 3);
    #pragma unroll
    for (int nb = 0; nb < 4; nb++) {
        int n0 = colBase + nb * 8;
        float2 bv = *(const float2*)(bias + n0);
        #pragma unroll
        for (int mb = 0; mb < 4; mb++) {
            int m0 = rowBase + mb * 16;
            float2 v0 = { acc[mb][nb][0] + bv.x, acc[mb][nb][1] + bv.y };
            float2 v1 = { acc[mb][nb][2] + bv.x, acc[mb][nb][3] + bv.y };
            *(float2*)(out + (size_t)m0 * OUTF + n0) = v0;
            *(float2*)(out + (size_t)(m0 + 8) * OUTF + n0) = v1;
        }
    }
}

// ---------------------------------------------------------------------------
// launch
// ---------------------------------------------------------------------------
extern "C" void kernel_launch(void* const* d_in, const int* in_sizes, int n_in,
                              void* d_out, int out_size) {
    const float* x      = (const float*)d_in[0];
    const int*   qw     = (const int*)d_in[1];
    const int*   qz     = (const int*)d_in[2];
    const float* scales = (const float*)d_in[3];
    const float* bias   = (const float*)d_in[4];
    float* out = (float*)d_out;

    static int configured = 0;
    if (!configured) {
        cudaFuncSetAttribute(gemm_kernel, cudaFuncAttributeMaxDynamicSharedMemorySize, SMEM_DYN);
        configured = 1;
    }

    dim3 gx(MT, KCHUNKS);
    prep_x_kernel<<<gx, 256>>>(x);

    dim3 gw(OUTF / 256, INF / 8);
    prep_w_kernel<<<gw, 256>>>(qw, qz, scales);

    dim3 gg(MT, NT);
    gemm_kernel<<<gg, 512, SMEM_DYN>>>(bias, out);
}

// round 10
// speedup vs baseline: 1.3481x; 1.1387x over previous
#include <cuda_runtime.h>
#include <cuda_fp16.h>
#include <cstdint>

// ---------------------------------------------------------------------------
// x[4096,8192] fp32, qweight[1024,8192] i32 (4-bit packed along k),
// qzeros[64,1024] i32, scales[64,8192] fp32, bias[8192] fp32
//   -> out[4096,8192] fp32.
// Two-pass: ONE merged prep kernel writes pre-swizzled fp16 tiles for both
// operands (exact-fp16 dequant); gemm is the round-6 champion config:
// 8 warps of 64x64, register double-buffered ldmatrix fragments,
// mma.sync.m16n8k16 fp16->fp32 (tcgen05 is rejected by the harness's
// compute_103 virtual arch).
// ---------------------------------------------------------------------------
#define TOKENS   4096
#define INF      8192
#define OUTF     8192
#define KCHUNK   64
#define KCHUNKS  128            // INF / KCHUNK
#define MT       32             // TOKENS / 128
#define NT       32             // OUTF / 256
#define A_TILE   16384          // 128 m-rows * 128B (64 fp16, K-major, SW128)
#define B_TILE   32768          // 256 n-rows * 128B
#define STAGE_BYTES (A_TILE + B_TILE)
#define NSTAGES  4
#define SMEM_DYN (NSTAGES * STAGE_BYTES + 1024)   // + align pad

// scratch: tile-major, pre-swizzled fp16 operands (device globals, no alloc)
__device__ __align__(1024) unsigned char g_xt[(size_t)MT * KCHUNKS * A_TILE]; // 64 MB
__device__ __align__(1024) unsigned char g_wt[(size_t)NT * KCHUNKS * B_TILE]; // 128 MB

// ---------------------------------------------------------------------------
// helpers
// ---------------------------------------------------------------------------
__device__ __forceinline__ uint32_t smem_to_u32(const void* p) {
    uint32_t a;
    asm("{ .reg .u64 t; cvta.to.shared.u64 t, %1; cvt.u32.u64 %0, t; }" : "=r"(a) : "l"(p));
    return a;
}

#define SWZ(o) ((o) ^ (((o) >> 3) & 0x70))

__device__ __forceinline__ void cp_async16(uint32_t dst, const void* src) {
    asm volatile("cp.async.cg.shared.global [%0], [%1], 16;" :: "r"(dst), "l"(src));
}
#define CP_COMMIT() asm volatile("cp.async.commit_group;" ::: "memory")
#define CP_WAIT(n)  asm volatile("cp.async.wait_group %0;" :: "n"(n) : "memory")

__device__ __forceinline__ void ldsm4(uint32_t& r0, uint32_t& r1, uint32_t& r2, uint32_t& r3,
                                      uint32_t addr) {
    asm volatile("ldmatrix.sync.aligned.m8n8.x4.shared.b16 {%0,%1,%2,%3}, [%4];"
        : "=r"(r0), "=r"(r1), "=r"(r2), "=r"(r3) : "r"(addr));
}

__device__ __forceinline__ void mma16816(float* c,
    uint32_t a0, uint32_t a1, uint32_t a2, uint32_t a3, uint32_t b0, uint32_t b1) {
    asm volatile("mma.sync.aligned.m16n8k16.row.col.f32.f16.f16.f32 "
        "{%0,%1,%2,%3}, {%4,%5,%6,%7}, {%8,%9}, {%0,%1,%2,%3};"
        : "+f"(c[0]), "+f"(c[1]), "+f"(c[2]), "+f"(c[3])
        : "r"(a0), "r"(a1), "r"(a2), "r"(a3), "r"(b0), "r"(b1));
}

union HU { unsigned u; __half2 h; };
__device__ __forceinline__ unsigned h2u(__half2 h) { HU t; t.h = h; return t.u; }
__device__ __forceinline__ __half2 u2h(unsigned u) { HU t; t.u = u; return t.h; }

// ---------------------------------------------------------------------------
// merged prep: blocks [0, 4096) convert x; blocks [4096, 20480) dequant W.
// Both write tile-major SW128 fp16 with k-octet permutation (k0,k4)(k1,k5)...
// The DRAM-bound x path and the issue-bound w path co-run on the chip.
// grid 20480 x 256 threads
// ---------------------------------------------------------------------------
__global__ void __launch_bounds__(256) prep_kernel(
    const float* __restrict__ x,
    const int* __restrict__ qw, const int* __restrict__ qz,
    const float* __restrict__ sc)
{
    int b = blockIdx.x;
    if (b < 4096) {
        // ---- x: fp32 -> fp16, tile (mt, kc) ----
        int mt = b >> 7;                // 0..31
        int kc = b & 127;               // 0..127
        unsigned char* tile = g_xt + ((size_t)(mt * KCHUNKS + kc)) * A_TILE;
        const float* xrowbase = x + (size_t)mt * 128 * INF + (size_t)kc * KCHUNK;
        for (int u = threadIdx.x; u < 1024; u += 256) {   // 128 rows * 8 octets
            int row = u >> 3, oct = u & 7;
            const float4* p = (const float4*)(xrowbase + (size_t)row * INF + oct * 8);
            float4 a = p[0];
            float4 bb = p[1];
            uint4 o;
            o.x = h2u(__floats2half2_rn(a.x, bb.x));   // (k0, k4)
            o.y = h2u(__floats2half2_rn(a.y, bb.y));   // (k1, k5)
            o.z = h2u(__floats2half2_rn(a.z, bb.z));   // (k2, k6)
            o.w = h2u(__floats2half2_rn(a.w, bb.w));   // (k3, k7)
            *(uint4*)(tile + SWZ(row * 128 + oct * 16)) = o;
        }
    } else {
        // ---- W: int4 unpack + dequant -> fp16 (exact (1024+w)-(1024+z+1)) ----
        int b2 = b - 4096;              // 0..16383
        int kr = b2 >> 4;               // packed k-octet row, 0..1023
        int nb0 = (b2 & 15) * 512;      // n-slab base (512 wide, 2 per thread)
        int kc  = kr >> 3;              // 64-k chunk index
        int oct = kr & 7;               // octet within chunk
        int g   = kr >> 4;              // 128-k quant group
        const unsigned m = 0x000F000Fu, add = 0x64006400u;
        #pragma unroll
        for (int h = 0; h < 2; h++) {
            int n = nb0 + h * 256 + threadIdx.x;   // 0..8191
            unsigned q  = (unsigned)qw[(size_t)kr * OUTF + n];
            unsigned zq = (unsigned)qz[(size_t)g * (OUTF / 8) + (n >> 3)];
            unsigned z  = (zq >> ((n & 7) * 4)) & 0xF;
            unsigned zb = 0x6400u + z + 1u;        // fp16 bits of (1024+z+1), exact
            __half2 zh2 = u2h(zb | (zb << 16));
            __half2 sh2 = __float2half2_rn(sc[(size_t)g * OUTF + n]);
            unsigned v0 = (q & m) | add;           // (1024+k0, 1024+k4)
            unsigned v1 = ((q >> 4) & m) | add;    // (k1, k5)
            unsigned v2 = ((q >> 8) & m) | add;    // (k2, k6)
            unsigned v3 = ((q >> 12) & m) | add;   // (k3, k7)
            uint4 o;
            o.x = h2u(__hmul2(__hsub2(u2h(v0), zh2), sh2));
            o.y = h2u(__hmul2(__hsub2(u2h(v1), zh2), sh2));
            o.z = h2u(__hmul2(__hsub2(u2h(v2), zh2), sh2));
            o.w = h2u(__hmul2(__hsub2(u2h(v3), zh2), sh2));
            int nt = n >> 8;          // 256-wide n tile
            int rr = n & 255;         // n-row within tile
            unsigned char* tile = g_wt + ((size_t)(nt * KCHUNKS + kc)) * B_TILE;
            *(uint4*)(tile + SWZ(rr * 128 + oct * 16)) = o;
        }
    }
}

// ---------------------------------------------------------------------------
// gemm (round-6 champion): 128M x 256N per CTA, 8 warps (2x4) of 64x64,
// K in 64-chunks, 4-stage cp.async pipeline, mma.sync m16n8k16 fp16->fp32,
// register double-buffered ldmatrix fragments with cross-chunk prefetch.
// grid (MT, NT) = (32, 32), 256 threads
// ---------------------------------------------------------------------------
__global__ void __launch_bounds__(256, 1) gemm_kernel(
    const float* __restrict__ bias, float* __restrict__ out)
{
    extern __shared__ unsigned char smem_raw[];
    uint32_t base = (smem_to_u32(smem_raw) + 1023u) & ~1023u;

    int tid = threadIdx.x, wid = tid >> 5, lane = tid & 31;
    int wm = wid >> 2, wn = wid & 3;           // warp grid 2(m) x 4(n)
    int mt = blockIdx.x, nt = blockIdx.y;

    const unsigned char* gA = g_xt + (size_t)mt * KCHUNKS * A_TILE;
    const unsigned char* gB = g_wt + (size_t)nt * KCHUNKS * B_TILE;

    // cp.async stage fill: data is pre-swizzled in gmem -> verbatim 16B copies
    auto load_stage = [&](int chunk, int slot) {
        uint32_t sd = base + slot * STAGE_BYTES;
        const unsigned char* aS = gA + (size_t)chunk * A_TILE;
        const unsigned char* bS = gB + (size_t)chunk * B_TILE;
        #pragma unroll
        for (int i = 0; i < 4; i++)
            cp_async16(sd + (tid + 256 * i) * 16, aS + (size_t)(tid + 256 * i) * 16);
        #pragma unroll
        for (int i = 0; i < 8; i++)
            cp_async16(sd + A_TILE + (tid + 256 * i) * 16, bS + (size_t)(tid + 256 * i) * 16);
    };

    // ldmatrix per-lane geometry (validated rounds 3/6/7/8/9).
    int gq = lane >> 3, r = lane & 7;
    int aRow0 = wm * 64 + (gq & 1) * 8 + r;   int aGh = gq >> 1;
    int bRow0 = wn * 64 + (gq >> 1) * 8 + r;  int bGl = gq & 1;

    float acc[4][8][4];
    #pragma unroll
    for (int i = 0; i < 4; i++)
        #pragma unroll
        for (int j = 0; j < 8; j++)
            #pragma unroll
            for (int k = 0; k < 4; k++) acc[i][j][k] = 0.f;

    // double-buffered fragments (all indices compile-time)
    uint32_t afr[2][4][4], bfr[2][4][4];

#define PREFETCH(BUF, BASE, C) do {                                               \
        uint32_t _sA = (BASE), _sB = (BASE) + A_TILE;                             \
        _Pragma("unroll")                                                         \
        for (int mb = 0; mb < 4; mb++) {                                          \
            uint32_t off = (uint32_t)(aRow0 + mb * 16) * 128u                     \
                         + (uint32_t)(((2 * (C) + aGh) ^ r) << 4);                \
            ldsm4(afr[BUF][mb][0], afr[BUF][mb][1], afr[BUF][mb][2],              \
                  afr[BUF][mb][3], _sA + off);                                    \
        }                                                                         \
        _Pragma("unroll")                                                         \
        for (int p = 0; p < 4; p++) {                                             \
            uint32_t off = (uint32_t)(bRow0 + p * 16) * 128u                      \
                         + (uint32_t)(((2 * (C) + bGl) ^ r) << 4);                \
            ldsm4(bfr[BUF][p][0], bfr[BUF][p][1], bfr[BUF][p][2],                 \
                  bfr[BUF][p][3], _sB + off);                                     \
        }                                                                         \
    } while (0)

#define MMASTEP(BUF) do {                                                         \
        _Pragma("unroll")                                                         \
        for (int mb = 0; mb < 4; mb++)                                            \
            _Pragma("unroll")                                                     \
            for (int p = 0; p < 4; p++) {                                         \
                mma16816(acc[mb][2 * p],     afr[BUF][mb][0], afr[BUF][mb][1],    \
                         afr[BUF][mb][2], afr[BUF][mb][3],                        \
                         bfr[BUF][p][0], bfr[BUF][p][1]);                         \
                mma16816(acc[mb][2 * p + 1], afr[BUF][mb][0], afr[BUF][mb][1],    \
                         afr[BUF][mb][2], afr[BUF][mb][3],                        \
                         bfr[BUF][p][2], bfr[BUF][p][3]);                         \
            }                                                                     \
    } while (0)

    // prologue: stages 0..2 in flight, then stage 0 ready -> preload step 0
    #pragma unroll
    for (int j = 0; j < NSTAGES - 1; j++) { load_stage(j, j); CP_COMMIT(); }
    CP_WAIT(2);
    __syncthreads();
    PREFETCH(0, base, 0);

    #pragma unroll 1
    for (int it = 0; it < KCHUNKS; it++) {
        // stages <= it+1 complete & visible after this barrier
        CP_WAIT(1);
        __syncthreads();
        if (it + NSTAGES - 1 < KCHUNKS) load_stage(it + NSTAGES - 1, (it + NSTAGES - 1) & 3);
        CP_COMMIT();

        uint32_t cbase = base + (it & 3) * STAGE_BYTES;
        uint32_t nbase = base + ((it + 1) & 3) * STAGE_BYTES;
        PREFETCH(1, cbase, 1); MMASTEP(0);
        PREFETCH(0, cbase, 2); MMASTEP(1);
        PREFETCH(1, cbase, 3); MMASTEP(0);
        PREFETCH(0, nbase, 0); MMASTEP(1);   // cross-chunk: next chunk's step 0
    }
    CP_WAIT(0);   // drain outstanding copies before exit

#undef PREFETCH
#undef MMASTEP

    // epilogue: acc frag (c0,c1)=(row l/4, col 2(l%4),+1), (c2,c3)=(row+8, same)
    int rowBase = mt * 128 + wm * 64 + (lane >> 2);
    int colBase = nt * 256 + wn * 64 + 2 * (lane & 3);
    #pragma unroll
    for (int nb = 0; nb < 8; nb++) {
        int n0 = colBase + nb * 8;
        float2 bv = *(const float2*)(bias + n0);
        #pragma unroll
        for (int mb = 0; mb < 4; mb++) {
            int m0 = rowBase + mb * 16;
            float2 v0 = { acc[mb][nb][0] + bv.x, acc[mb][nb][1] + bv.y };
            float2 v1 = { acc[mb][nb][2] + bv.x, acc[mb][nb][3] + bv.y };
            *(float2*)(out + (size_t)m0 * OUTF + n0) = v0;
            *(float2*)(out + (size_t)(m0 + 8) * OUTF + n0) = v1;
        }
    }
}

// ---------------------------------------------------------------------------
// launch
// ---------------------------------------------------------------------------
extern "C" void kernel_launch(void* const* d_in, const int* in_sizes, int n_in,
                              void* d_out, int out_size) {
    const float* x      = (const float*)d_in[0];
    const int*   qw     = (const int*)d_in[1];
    const int*   qz     = (const int*)d_in[2];
    const float* scales = (const float*)d_in[3];
    const float* bias   = (const float*)d_in[4];
    float* out = (float*)d_out;

    static int configured = 0;
    if (!configured) {
        cudaFuncSetAttribute(gemm_kernel, cudaFuncAttributeMaxDynamicSharedMemorySize, SMEM_DYN);
        configured = 1;
    }

    prep_kernel<<<20480, 256>>>(x, qw, qz, scales);

    dim3 gg(MT, NT);
    gemm_kernel<<<gg, 256, SMEM_DYN>>>(bias, out);
}

// round 12
// speedup vs baseline: 1.4338x; 1.0636x over previous
#include <cuda_runtime.h>
#include <cuda_fp16.h>
#include <cstdint>

// ---------------------------------------------------------------------------
// x[4096,8192] fp32, qweight[1024,8192] i32 (4-bit packed along k),
// qzeros[64,1024] i32, scales[64,8192] fp32, bias[8192] fp32
//   -> out[4096,8192] fp32.
// Two-pass: merged prep kernel writes pre-swizzled fp16 tiles (exact-fp16
// dequant); gemm = 8 warps of 64x64, register double-buffered ldmatrix
// fragments, mma.sync.m16n8k16 fp16->fp32, SUPERSTAGE pipeline (2 chunks per
// iteration -> 64 barriers instead of 128). tcgen05 is rejected by the
// harness's compute_103 virtual arch.
// ---------------------------------------------------------------------------
#define TOKENS   4096
#define INF      8192
#define OUTF     8192
#define KCHUNK   64
#define KCHUNKS  128            // INF / KCHUNK
#define NSUPER   64             // KCHUNKS / 2
#define MT       32             // TOKENS / 128
#define NT       32             // OUTF / 256
#define A_TILE   16384          // 128 m-rows * 128B (64 fp16, K-major, SW128)
#define B_TILE   32768          // 256 n-rows * 128B
#define STAGE_BYTES (A_TILE + B_TILE)
#define NSTAGES  4
#define SMEM_DYN (NSTAGES * STAGE_BYTES + 1024)   // + align pad

// scratch: tile-major, pre-swizzled fp16 operands (device globals, no alloc)
__device__ __align__(1024) unsigned char g_xt[(size_t)MT * KCHUNKS * A_TILE]; // 64 MB
__device__ __align__(1024) unsigned char g_wt[(size_t)NT * KCHUNKS * B_TILE]; // 128 MB

// ---------------------------------------------------------------------------
// helpers
// ---------------------------------------------------------------------------
__device__ __forceinline__ uint32_t smem_to_u32(const void* p) {
    uint32_t a;
    asm("{ .reg .u64 t; cvta.to.shared.u64 t, %1; cvt.u32.u64 %0, t; }" : "=r"(a) : "l"(p));
    return a;
}

#define SWZ(o) ((o) ^ (((o) >> 3) & 0x70))

__device__ __forceinline__ void cp_async16(uint32_t dst, const void* src) {
    asm volatile("cp.async.cg.shared.global [%0], [%1], 16;" :: "r"(dst), "l"(src));
}
#define CP_COMMIT() asm volatile("cp.async.commit_group;" ::: "memory")
#define CP_WAIT(n)  asm volatile("cp.async.wait_group %0;" :: "n"(n) : "memory")

__device__ __forceinline__ void ldsm4(uint32_t& r0, uint32_t& r1, uint32_t& r2, uint32_t& r3,
                                      uint32_t addr) {
    asm volatile("ldmatrix.sync.aligned.m8n8.x4.shared.b16 {%0,%1,%2,%3}, [%4];"
        : "=r"(r0), "=r"(r1), "=r"(r2), "=r"(r3) : "r"(addr));
}

__device__ __forceinline__ void mma16816(float* c,
    uint32_t a0, uint32_t a1, uint32_t a2, uint32_t a3, uint32_t b0, uint32_t b1) {
    asm volatile("mma.sync.aligned.m16n8k16.row.col.f32.f16.f16.f32 "
        "{%0,%1,%2,%3}, {%4,%5,%6,%7}, {%8,%9}, {%0,%1,%2,%3};"
        : "+f"(c[0]), "+f"(c[1]), "+f"(c[2]), "+f"(c[3])
        : "r"(a0), "r"(a1), "r"(a2), "r"(a3), "r"(b0), "r"(b1));
}

union HU { unsigned u; __half2 h; };
__device__ __forceinline__ unsigned h2u(__half2 h) { HU t; t.h = h; return t.u; }
__device__ __forceinline__ __half2 u2h(unsigned u) { HU t; t.u = u; return t.h; }

// ---------------------------------------------------------------------------
// merged prep: blocks [0, 4096) convert x; blocks [4096, 8192) dequant W.
// Both write tile-major SW128 fp16 with k-octet permutation (k0,k4)(k1,k5)...
// W path: one thread per (n, 64k-chunk) -> 8 octet rows, so the zero-point
// and scale are loaded ONCE per 8 packed int32 (same per-element math/order
// as before -> bit-identical output).
// grid 8192 x 256 threads
// ---------------------------------------------------------------------------
__global__ void __launch_bounds__(256) prep_kernel(
    const float* __restrict__ x,
    const int* __restrict__ qw, const int* __restrict__ qz,
    const float* __restrict__ sc)
{
    int b = blockIdx.x;
    if (b < 4096) {
        // ---- x: fp32 -> fp16, tile (mt, kc) ----
        int mt = b >> 7;                // 0..31
        int kc = b & 127;               // 0..127
        unsigned char* tile = g_xt + ((size_t)(mt * KCHUNKS + kc)) * A_TILE;
        const float* xrowbase = x + (size_t)mt * 128 * INF + (size_t)kc * KCHUNK;
        for (int u = threadIdx.x; u < 1024; u += 256) {   // 128 rows * 8 octets
            int row = u >> 3, oct = u & 7;
            const float4* p = (const float4*)(xrowbase + (size_t)row * INF + oct * 8);
            float4 a = p[0];
            float4 bb = p[1];
            uint4 o;
            o.x = h2u(__floats2half2_rn(a.x, bb.x));   // (k0, k4)
            o.y = h2u(__floats2half2_rn(a.y, bb.y));   // (k1, k5)
            o.z = h2u(__floats2half2_rn(a.z, bb.z));   // (k2, k6)
            o.w = h2u(__floats2half2_rn(a.w, bb.w));   // (k3, k7)
            *(uint4*)(tile + SWZ(row * 128 + oct * 16)) = o;
        }
    } else {
        // ---- W: int4 unpack + dequant -> fp16 (exact (1024+w)-(1024+z+1)) ----
        int b2 = b - 4096;              // 0..4095
        int kc = b2 & 127;              // 64-k chunk index
        int n  = (b2 >> 7) * 256 + threadIdx.x;   // 0..8191
        int g  = kc >> 1;               // 128-k quant group

        unsigned zq = (unsigned)qz[(size_t)g * (OUTF / 8) + (n >> 3)];
        unsigned z  = (zq >> ((n & 7) * 4)) & 0xF;
        unsigned zb = 0x6400u + z + 1u;        // fp16 bits of (1024+z+1), exact
        __half2 zh2 = u2h(zb | (zb << 16));
        __half2 sh2 = __float2half2_rn(sc[(size_t)g * OUTF + n]);

        int rr = n & 255;               // n-row within 256-wide tile
        unsigned char* tile = g_wt + ((size_t)((n >> 8) * KCHUNKS + kc)) * B_TILE;
        const int* qrow = qw + (size_t)(kc * 8) * OUTF + n;
        const unsigned m = 0x000F000Fu, add = 0x64006400u;
        #pragma unroll
        for (int oct = 0; oct < 8; oct++) {
            unsigned q = (unsigned)qrow[(size_t)oct * OUTF];
            unsigned v0 = (q & m) | add;           // (1024+k0, 1024+k4)
            unsigned v1 = ((q >> 4) & m) | add;    // (k1, k5)
            unsigned v2 = ((q >> 8) & m) | add;    // (k2, k6)
            unsigned v3 = ((q >> 12) & m) | add;   // (k3, k7)
            uint4 o;
            o.x = h2u(__hmul2(__hsub2(u2h(v0), zh2), sh2));
            o.y = h2u(__hmul2(__hsub2(u2h(v1), zh2), sh2));
            o.z = h2u(__hmul2(__hsub2(u2h(v2), zh2), sh2));
            o.w = h2u(__hmul2(__hsub2(u2h(v3), zh2), sh2));
            *(uint4*)(tile + SWZ(rr * 128 + oct * 16)) = o;
        }
    }
}

// ---------------------------------------------------------------------------
// gemm: 128M x 256N per CTA, 8 warps (2x4) of 64x64, K in 64-chunks,
// SUPERSTAGE pipeline: 2 chunks (96KB) per iteration, 2 ping-pong buffers of
// 2 chunk-slots each; one CP_WAIT + one __syncthreads per superstage.
// Register double-buffered ldmatrix fragments across all 8 k16 steps.
// grid (MT, NT) = (32, 32), 256 threads
// ---------------------------------------------------------------------------
__global__ void __launch_bounds__(256, 1) gemm_kernel(
    const float* __restrict__ bias, float* __restrict__ out)
{
    extern __shared__ unsigned char smem_raw[];
    uint32_t base = (smem_to_u32(smem_raw) + 1023u) & ~1023u;

    int tid = threadIdx.x, wid = tid >> 5, lane = tid & 31;
    int wm = wid >> 2, wn = wid & 3;           // warp grid 2(m) x 4(n)
    int mt = blockIdx.x, nt = blockIdx.y;

    const unsigned char* gA = g_xt + (size_t)mt * KCHUNKS * A_TILE;
    const unsigned char* gB = g_wt + (size_t)nt * KCHUNKS * B_TILE;

    // cp.async fill of one chunk slot (data pre-swizzled -> verbatim copies)
    auto load_stage = [&](int chunk, int slot) {
        uint32_t sd = base + slot * STAGE_BYTES;
        const unsigned char* aS = gA + (size_t)chunk * A_TILE;
        const unsigned char* bS = gB + (size_t)chunk * B_TILE;
        #pragma unroll
        for (int i = 0; i < 4; i++)
            cp_async16(sd + (tid + 256 * i) * 16, aS + (size_t)(tid + 256 * i) * 16);
        #pragma unroll
        for (int i = 0; i < 8; i++)
            cp_async16(sd + A_TILE + (tid + 256 * i) * 16, bS + (size_t)(tid + 256 * i) * 16);
    };

    // ldmatrix per-lane geometry (validated rounds 3/6/7/8/9/10).
    int gq = lane >> 3, r = lane & 7;
    int aRow0 = wm * 64 + (gq & 1) * 8 + r;   int aGh = gq >> 1;
    int bRow0 = wn * 64 + (gq >> 1) * 8 + r;  int bGl = gq & 1;

    float acc[4][8][4];
    #pragma unroll
    for (int i = 0; i < 4; i++)
        #pragma unroll
        for (int j = 0; j < 8; j++)
            #pragma unroll
            for (int k = 0; k < 4; k++) acc[i][j][k] = 0.f;

    // double-buffered fragments (all indices compile-time)
    uint32_t afr[2][4][4], bfr[2][4][4];

#define PREFETCH(BUF, BASE, C) do {                                               \
        uint32_t _sA = (BASE), _sB = (BASE) + A_TILE;                             \
        _Pragma("unroll")                                                         \
        for (int mb = 0; mb < 4; mb++) {                                          \
            uint32_t off = (uint32_t)(aRow0 + mb * 16) * 128u                     \
                         + (uint32_t)(((2 * (C) + aGh) ^ r) << 4);                \
            ldsm4(afr[BUF][mb][0], afr[BUF][mb][1], afr[BUF][mb][2],              \
                  afr[BUF][mb][3], _sA + off);                                    \
        }                                                                         \
        _Pragma("unroll")                                                         \
        for (int p = 0; p < 4; p++) {                                             \
            uint32_t off = (uint32_t)(bRow0 + p * 16) * 128u                      \
                         + (uint32_t)(((2 * (C) + bGl) ^ r) << 4);                \
            ldsm4(bfr[BUF][p][0], bfr[BUF][p][1], bfr[BUF][p][2],                 \
                  bfr[BUF][p][3], _sB + off);                                     \
        }                                                                         \
    } while (0)

#define MMASTEP(BUF) do {                                                         \
        _Pragma("unroll")                                                         \
        for (int mb = 0; mb < 4; mb++)                                            \
            _Pragma("unroll")                                                     \
            for (int p = 0; p < 4; p++) {                                         \
                mma16816(acc[mb][2 * p],     afr[BUF][mb][0], afr[BUF][mb][1],    \
                         afr[BUF][mb][2], afr[BUF][mb][3],                        \
                         bfr[BUF][p][0], bfr[BUF][p][1]);                         \
                mma16816(acc[mb][2 * p + 1], afr[BUF][mb][0], afr[BUF][mb][1],    \
                         afr[BUF][mb][2], afr[BUF][mb][3],                        \
                         bfr[BUF][p][2], bfr[BUF][p][3]);                         \
            }                                                                     \
    } while (0)

    // prologue: superstages 0 (chunks 0,1) and 1 (chunks 2,3) in flight,
    // one commit group per superstage.
    load_stage(0, 0); load_stage(1, 1); CP_COMMIT();
    load_stage(2, 2); load_stage(3, 3); CP_COMMIT();
    CP_WAIT(1);            // superstage 0 complete
    __syncthreads();       // ...and visible
    PREFETCH(0, base, 0);  // chunk 0, step 0

    #pragma unroll 1
    for (int t = 0; t < NSUPER; t++) {
        uint32_t cb0 = base + ((2 * t) & 3) * STAGE_BYTES;     // chunk 2t
        uint32_t cb1 = cb0 + STAGE_BYTES;                      // chunk 2t+1

        PREFETCH(1, cb0, 1); MMASTEP(0);
        PREFETCH(0, cb0, 2); MMASTEP(1);
        PREFETCH(1, cb0, 3); MMASTEP(0);
        PREFETCH(0, cb1, 0); MMASTEP(1);
        PREFETCH(1, cb1, 1); MMASTEP(0);
        PREFETCH(0, cb1, 2); MMASTEP(1);
        PREFETCH(1, cb1, 3); MMASTEP(0);
        MMASTEP(1);

        CP_WAIT(0);        // superstage t+1 (loaded during this compute) done
        __syncthreads();   // reads of buffer t&1 done in all threads; publish
        if (t + 2 < NSUPER) {   // refill just-consumed buffer with superstage t+2
            load_stage(2 * t + 4, (2 * t + 4) & 3);
            load_stage(2 * t + 5, (2 * t + 5) & 3);
            CP_COMMIT();
        }
        if (t + 1 < NSUPER)     // first fragment of next superstage
            PREFETCH(0, base + ((2 * t + 2) & 3) * STAGE_BYTES, 0);
    }

#undef PREFETCH
#undef MMASTEP

    // epilogue: acc frag (c0,c1)=(row l/4, col 2(l%4),+1), (c2,c3)=(row+8, same)
    int rowBase = mt * 128 + wm * 64 + (lane >> 2);
    int colBase = nt * 256 + wn * 64 + 2 * (lane & 3);
    #pragma unroll
    for (int nb = 0; nb < 8; nb++) {
        int n0 = colBase + nb * 8;
        float2 bv = *(const float2*)(bias + n0);
        #pragma unroll
        for (int mb = 0; mb < 4; mb++) {
            int m0 = rowBase + mb * 16;
            float2 v0 = { acc[mb][nb][0] + bv.x, acc[mb][nb][1] + bv.y };
            float2 v1 = { acc[mb][nb][2] + bv.x, acc[mb][nb][3] + bv.y };
            *(float2*)(out + (size_t)m0 * OUTF + n0) = v0;
            *(float2*)(out + (size_t)(m0 + 8) * OUTF + n0) = v1;
        }
    }
}

// ---------------------------------------------------------------------------
// launch
// ---------------------------------------------------------------------------
extern "C" void kernel_launch(void* const* d_in, const int* in_sizes, int n_in,
                              void* d_out, int out_size) {
    const float* x      = (const float*)d_in[0];
    const int*   qw     = (const int*)d_in[1];
    const int*   qz     = (const int*)d_in[2];
    const float* scales = (const float*)d_in[3];
    const float* bias   = (const float*)d_in[4];
    float* out = (float*)d_out;

    static int configured = 0;
    if (!configured) {
        cudaFuncSetAttribute(gemm_kernel, cudaFuncAttributeMaxDynamicSharedMemorySize, SMEM_DYN);
        configured = 1;
    }

    prep_kernel<<<8192, 256>>>(x, qw, qz, scales);

    dim3 gg(MT, NT);
    gemm_kernel<<<gg, 256, SMEM_DYN>>>(bias, out);
}